// round 10
// baseline (speedup 1.0000x reference)
#include <cuda_runtime.h>
#include <cstdint>

#define Bn 64
#define Tn 64
#define Dn 64
#define Pn 63
typedef unsigned long long ull;

// ---------------- device scratch ----------------
__device__ __align__(16) float g_emb[Tn * Bn * 128];         // [t][b][e]
__device__ __align__(16) ull   g_embP[Tn * 32 * 128];        // [t][rpg][e]
__device__ __align__(16) ull   g_giP[64 * 2 * 32 * 3 * 128]; // [t][gru][rpg][gate][k]
__device__ __align__(16) ull   g_xP[64 * 32 * 64];           // [j][bp][d]
__device__ __align__(16) float g_WiaT[128 * 384];            // [e][u]
__device__ __align__(16) float g_WibT[128 * 384];
// DUPLICATED per-warp Wh: [w 8][tile 16][li 8][ (wr,wr)(wz,wz) x32 | (wn,wn) x32 ] (192 floats/row)
__device__ __align__(16) float g_WhW2[8 * 16 * 8 * 192];
// DUPLICATED band Wb: [band 4][tile 4][il 32][ (wv,wv) x32 ] (64 floats/row)
__device__ __align__(16) float g_WbW2[4 * 4 * 32 * 64];
__device__ __align__(16) float g_WembT[64 * 128];            // [d][e]
__device__ __align__(16) float g_WoWemb[128 * 64];           // [e][d]

// ---------------- f32x2 helpers ----------------
__device__ __forceinline__ ull pack2(float x, float y) {
    ull r; asm("mov.b64 %0, {%1,%2};" : "=l"(r) : "f"(x), "f"(y)); return r;
}
__device__ __forceinline__ float2 unpack2(ull v) {
    float2 r; asm("mov.b64 {%0,%1}, %2;" : "=f"(r.x), "=f"(r.y) : "l"(v)); return r;
}
__device__ __forceinline__ ull fma2(ull a, ull b, ull c) {
    ull d; asm("fma.rn.f32x2 %0, %1, %2, %3;" : "=l"(d) : "l"(a), "l"(b), "l"(c)); return d;
}
__device__ __forceinline__ ull mul2(ull a, ull b) {
    ull d; asm("mul.rn.f32x2 %0, %1, %2;" : "=l"(d) : "l"(a), "l"(b)); return d;
}
__device__ __forceinline__ float sigmoidf_(float v) {
    return __fdividef(1.f, 1.f + __expf(-v));
}
__device__ __forceinline__ float tanhfast(float v) {
    float e = __expf(2.f * v);
    return 1.f - __fdividef(2.f, e + 1.f);
}
__device__ __forceinline__ float gru_step(float ir, float iz, float in_,
                                          float hr, float hz, float hn, float h) {
    float r = sigmoidf_(ir + hr);
    float z = sigmoidf_(iz + hz);
    float n = tanhfast(in_ + r * hn);
    return n + z * (h - n);
}

// ---------------- cp.async helpers ----------------
__device__ __forceinline__ void cp16(uint32_t dst, const void* src) {
    asm volatile("cp.async.cg.shared.global [%0], [%1], 16;\n" :: "r"(dst), "l"(src));
}
__device__ __forceinline__ void cp_commit() {
    asm volatile("cp.async.commit_group;\n" ::: "memory");
}
__device__ __forceinline__ void cp_wait1() {
    asm volatile("cp.async.wait_group 1;\n" ::: "memory");
}
__device__ __forceinline__ void cp_wait0() {
    asm volatile("cp.async.wait_group 0;\n" ::: "memory");
}

// ---------------- prep ----------------
__global__ void prep_transpose(const float* __restrict__ x,
                               const float* __restrict__ Wh_a,
                               const float* __restrict__ Wh_b,
                               const float* __restrict__ Wi_a,
                               const float* __restrict__ Wi_b,
                               const float* __restrict__ Wb,
                               const float* __restrict__ W_emb,
                               const float* __restrict__ Wo) {
    int idx = blockIdx.x * blockDim.x + threadIdx.x;
    int stride = gridDim.x * blockDim.x;
    for (int n = idx; n < 128 * 384; n += stride) {
        int u = n % 384, i = n / 384;
        g_WiaT[n] = Wi_a[u * 128 + i];
        g_WibT[n] = Wi_b[u * 128 + i];
    }
    // duplicated Wh slices
    for (int n = idx; n < 8 * 128 * 32; n += stride) {
        int w = n >> 12;
        int rem = n & 4095;
        int i = rem >> 5, kk = rem & 31;
        int gru = w >> 2, band = w & 3;
        int kq = band * 32 + kk;
        const float* Wh = gru ? Wh_b : Wh_a;
        float wr = Wh[kq * 128 + i];
        float wz = Wh[(128 + kq) * 128 + i];
        float wn = Wh[(256 + kq) * 128 + i];
        int tl = i >> 3, li = i & 7;
        int base = ((w * 16 + tl) * 8 + li) * 192;
        g_WhW2[base + 4 * kk]     = wr;
        g_WhW2[base + 4 * kk + 1] = wr;
        g_WhW2[base + 4 * kk + 2] = wz;
        g_WhW2[base + 4 * kk + 3] = wz;
        g_WhW2[base + 128 + 2 * kk]     = wn;
        g_WhW2[base + 128 + 2 * kk + 1] = wn;
    }
    // duplicated Wb band slices
    for (int n = idx; n < 4 * 128 * 32; n += stride) {
        int band = n >> 12;
        int rem = n & 4095;
        int i = rem >> 5, kk = rem & 31;
        int tl = i >> 5, il = i & 31;
        float wv = Wb[(band * 32 + kk) * 128 + i];
        int base = ((band * 4 + tl) * 32 + il) * 64;
        g_WbW2[base + 2 * kk]     = wv;
        g_WbW2[base + 2 * kk + 1] = wv;
    }
    for (int n = idx; n < 64 * 128; n += stride) {
        int e = n % 128, d = n / 128;
        g_WembT[n] = W_emb[e * 64 + d];
    }
    for (int n = idx; n < 128 * 64; n += stride) {
        int d = n % 64, e = n / 64;
        g_WoWemb[n] = Wo[e] * W_emb[e * 64 + d];
    }
    for (int n = idx; n < 64 * 32 * 64; n += stride) {
        int j = n >> 11;
        int bp = (n >> 6) & 31;
        int d = n & 63;
        float x0 = x[((size_t)(2 * bp) * Tn + j) * Dn + d];
        float x1 = x[((size_t)(2 * bp + 1) * Tn + j) * Dn + d];
        g_xP[n] = pack2(x0, x1);
    }
}

// ---------------- emb ----------------
__global__ void emb_kernel(const float* __restrict__ x, const float* __restrict__ b_emb) {
    __shared__ float xs[64];
    int tb = blockIdx.x;
    int t_ = tb >> 6, b = tb & 63;
    int e = threadIdx.x;
    if (e < 64) xs[e] = x[((size_t)b * Tn + t_) * Dn + e];
    __syncthreads();
    float acc = 0.f;
#pragma unroll 8
    for (int d = 0; d < 64; ++d) acc = fmaf(g_WembT[d * 128 + e], xs[d], acc);
    g_emb[(size_t)tb * 128 + e] = acc + b_emb[e];
}

// ---------------- gi (packed) + emb packing ----------------
__global__ void gi_kernel(const float* __restrict__ bi_a, const float* __restrict__ bi_b) {
    __shared__ float es[128];
    int tb = blockIdx.x;
    int t_ = tb >> 6, b = tb & 63;
    int t = threadIdx.x;
    if (t < 128) es[t] = g_emb[(size_t)tb * 128 + t];
    __syncthreads();
    float* gf = (float*)g_giP;
    for (int u = t; u < 768; u += 256) {
        const float* WT;
        const float* bi;
        int gru, uu;
        if (u < 384) { WT = g_WiaT; bi = bi_a; gru = 0; uu = u; }
        else         { WT = g_WibT; bi = bi_b; gru = 1; uu = u - 384; }
        float acc = 0.f;
#pragma unroll 8
        for (int e = 0; e < 128; ++e) acc = fmaf(WT[e * 384 + uu], es[e], acc);
        int gate = uu >> 7, k = uu & 127;
        size_t ullIdx = (((size_t)(t_ * 2 + gru) * 32 + (b >> 1)) * 3 + gate) * 128 + k;
        gf[ullIdx * 2 + (b & 1)] = acc + bi[uu];
    }
    if ((b & 1) == 0 && t < 128) {
        g_embP[((size_t)t_ * 32 + (b >> 1)) * 128 + t] =
            pack2(g_emb[(size_t)tb * 128 + t], g_emb[(size_t)(tb + 1) * 128 + t]);
    }
}

// ---------------- main persistent kernel ----------------
// 256 threads, 8 warps. Per-warp 2-slot x 8KB rings; 20 tiles/step; 3 barriers/step.
#define RING_OFF   0                  // 8 warps x 2 slots x 8192 = 131072
#define SHH_OFF    131072             // ull [2][2][128][8] = 32768
#define BETA_OFF   163840             // ull [8][128] = 8192
#define WOW_OFF    172032             // float [128][64] = 32768
#define SCAL_OFF   204800             // scalars + Wa
#define SMEM_TOTAL 205824

__global__ __launch_bounds__(256, 1) void retain_main(
    const float* __restrict__ bh_a, const float* __restrict__ bh_b,
    const float* __restrict__ Wa, const float* __restrict__ ba,
    const float* __restrict__ bb, const float* __restrict__ Wo,
    const float* __restrict__ bo, int nq, float* __restrict__ out) {

    extern __shared__ char dsm[];
    float* smw = (float*)dsm;
    ull (*sh_h)[2][128][8] = (ull (*)[2][128][8])(dsm + SHH_OFF);
    ull (*sh_betaP)[128]   = (ull (*)[128])(dsm + BETA_OFF);
    float* sWo             = (float*)(dsm + WOW_OFF);
    float* sh_preA  = (float*)(dsm + SCAL_OFF);    // [16]
    float* sh_m     = sh_preA + 16;                // [16]
    float* sh_l     = sh_preA + 32;                // [16]
    ull*   sh_scaleP = (ull*)(sh_preA + 48);       // [8]
    ull*   sh_wP     = (ull*)(sh_preA + 64);       // [8]
    float* sh_Wa    = sh_preA + 80;                // [128]

    const int t = threadIdx.x;
    const int pb = blockIdx.x >> 2;
    const int chunkI = blockIdx.x & 3;
    const int b0 = chunkI * 16;

    const int w = t >> 5;
    const int lane = t & 31;
    const int gru = t >> 7;
    const int k = t & 127;
    const int band = w & 3;
    const int kk = lane;
    const int q = t >> 6;
    (void)band;

    const float* bh = gru ? bh_b : bh_a;
    const float bhr = bh[k], bhz = bh[128 + k], bhn = bh[256 + k];
    const float ba0 = ba[0], bbk = bb[k];
    const int base = Pn - nq;

    for (int n = t; n < 8192; n += 256) sWo[n] = g_WoWemb[n];
    if (t < 128) sh_Wa[t] = Wa[t];

    const bool seg2 = (pb < 31) && (pb >= base);
    const int totalSteps = (63 - pb) + (seg2 ? pb + 1 : 0);
    const int totalTiles = 20 * totalSteps;

    uint32_t ringB = (uint32_t)__cvta_generic_to_shared(dsm) + (uint32_t)(w * 16384);
    int issIdx = 0, issM = 0, issSlot = 0, consSlot = 0;

#define ISSUE_ONE() do {                                                        \
        if (issIdx < totalTiles) {                                              \
            const char* _src; int _bytes;                                       \
            if (issM < 16) { _src = (const char*)g_WhW2 + (size_t)(w * 16 + issM) * 6144; _bytes = 6144; } \
            else { _src = (const char*)g_WbW2 + (size_t)((w & 3) * 4 + (issM - 16)) * 8192; _bytes = 8192; } \
            uint32_t _d = ringB + (uint32_t)(issSlot * 8192);                   \
            for (int _o = lane * 16; _o < _bytes; _o += 512) cp16(_d + _o, _src + _o); \
            cp_commit();                                                        \
            ++issIdx; if (++issM == 20) issM = 0; issSlot ^= 1;                 \
        }                                                                       \
    } while (0)

#define WAITC() do {                                                            \
        if (issIdx < totalTiles) cp_wait1(); else cp_wait0();                   \
        __syncwarp();                                                           \
    } while (0)

    ISSUE_ONE();
    ISSUE_ONE();

    for (int seg = 0; seg < 2; ++seg) {
        const int p = seg ? pb : 62 - pb;
        if (seg && !seg2) break;

        for (int n = t; n < 2 * 128 * 8; n += 256)
            ((ull*)sh_h[0])[n] = 0ull;
        if (t < 16) { sh_m[t] = -1e30f; sh_l[t] = 0.f; }
        ull cacc[4] = {0ull, 0ull, 0ull, 0ull};
        ull gacc[2] = {0ull, 0ull};
        __syncthreads();

        for (int s = 0; s <= p; ++s) {
            const int j = p - s;
            const int cb = s & 1;
            const ull (*cur)[8]  = sh_h[cb][gru];
            ull (*nxtg)[8]       = sh_h[cb ^ 1][gru];
            const ull (*nxtA)[8] = sh_h[cb ^ 1][0];
            const ull (*nxtB)[8] = sh_h[cb ^ 1][1];

            // ---- phase 1: gh = h @ Wh^T, duplicated weights (no packs) ----
            ull aR[8], aZ[8], aN[8];
#pragma unroll
            for (int r = 0; r < 8; ++r) { aR[r] = 0ull; aZ[r] = 0ull; aN[r] = 0ull; }

#pragma unroll 1
            for (int tl = 0; tl < 16; ++tl) {
                WAITC();
                const float* wp = smw + w * 4096 + consSlot * 2048;
                consSlot ^= 1;
                const ull (*hrow)[8] = &cur[tl * 8];
#pragma unroll
                for (int li = 0; li < 8; ++li) {
                    const float* wrow = wp + li * 192;
                    ulonglong2 wrz = *(const ulonglong2*)(wrow + 4 * kk);
                    ull wr2 = wrz.x, wz2 = wrz.y;
                    ull wn2 = *(const ull*)(wrow + 128 + 2 * kk);
                    const ulonglong2* hp = reinterpret_cast<const ulonglong2*>(hrow[li]);
                    ulonglong2 hA = hp[0], hB = hp[1], hC = hp[2], hD = hp[3];
                    aR[0] = fma2(wr2, hA.x, aR[0]); aZ[0] = fma2(wz2, hA.x, aZ[0]); aN[0] = fma2(wn2, hA.x, aN[0]);
                    aR[1] = fma2(wr2, hA.y, aR[1]); aZ[1] = fma2(wz2, hA.y, aZ[1]); aN[1] = fma2(wn2, hA.y, aN[1]);
                    aR[2] = fma2(wr2, hB.x, aR[2]); aZ[2] = fma2(wz2, hB.x, aZ[2]); aN[2] = fma2(wn2, hB.x, aN[2]);
                    aR[3] = fma2(wr2, hB.y, aR[3]); aZ[3] = fma2(wz2, hB.y, aZ[3]); aN[3] = fma2(wn2, hB.y, aN[3]);
                    aR[4] = fma2(wr2, hC.x, aR[4]); aZ[4] = fma2(wz2, hC.x, aZ[4]); aN[4] = fma2(wn2, hC.x, aN[4]);
                    aR[5] = fma2(wr2, hC.y, aR[5]); aZ[5] = fma2(wz2, hC.y, aZ[5]); aN[5] = fma2(wn2, hC.y, aN[5]);
                    aR[6] = fma2(wr2, hD.x, aR[6]); aZ[6] = fma2(wz2, hD.x, aZ[6]); aN[6] = fma2(wn2, hD.x, aN[6]);
                    aR[7] = fma2(wr2, hD.y, aR[7]); aZ[7] = fma2(wz2, hD.y, aZ[7]); aN[7] = fma2(wn2, hD.y, aN[7]);
                }
                ISSUE_ONE();
            }

            // ---- phase 2: GRU update for 8 row-pairs at hidden k ----
            {
                const ull* gb = g_giP + (((size_t)(j * 2 + gru) * 32 + (b0 >> 1)) * 3) * 128 + k;
#pragma unroll
                for (int r = 0; r < 8; ++r) {
                    float2 gr = unpack2(gb[(size_t)r * 384]);
                    float2 gz = unpack2(gb[(size_t)r * 384 + 128]);
                    float2 gn = unpack2(gb[(size_t)r * 384 + 256]);
                    float2 hr = unpack2(aR[r]);
                    float2 hz = unpack2(aZ[r]);
                    float2 hn = unpack2(aN[r]);
                    float2 ho = unpack2(cur[k][r]);
                    float hx = gru_step(gr.x, gz.x, gn.x,
                                        hr.x + bhr, hz.x + bhz, hn.x + bhn, ho.x);
                    float hy = gru_step(gr.y, gz.y, gn.y,
                                        hr.y + bhr, hz.y + bhz, hn.y + bhn, ho.y);
                    nxtg[k][r] = pack2(hx, hy);
                }
            }
            __syncthreads();   // BAR1: h visible

            // ---- preA first (overlaps first Wb tile landing) ----
            {
#pragma unroll
                for (int rr = 0; rr < 2; ++rr) {
                    int r = w + 8 * rr;
                    float part = 0.f;
#pragma unroll
                    for (int ii = 0; ii < 4; ++ii) {
                        int i = lane + 32 * ii;
                        float2 hv = unpack2(nxtA[i][r >> 1]);
                        part = fmaf(sh_Wa[i], (r & 1) ? hv.y : hv.x, part);
                    }
#pragma unroll
                    for (int o = 16; o; o >>= 1)
                        part += __shfl_xor_sync(0xffffffffu, part, o);
                    if (lane == 0) sh_preA[r] = fmaf(0.5f, part, ba0);
                }
            }

            // ---- phase 3a: beta (rps 4gru..4gru+3, full i), duplicated Wb ----
            ull bacc[4] = {0ull, 0ull, 0ull, 0ull};
#pragma unroll 1
            for (int tb = 0; tb < 4; ++tb) {
                WAITC();
                const float* wbp = smw + w * 4096 + consSlot * 2048;
                consSlot ^= 1;
                const ull (*hb)[8] = &nxtB[tb * 32];
#pragma unroll 4
                for (int il = 0; il < 32; ++il) {
                    ull wb2 = *(const ull*)(wbp + il * 64 + 2 * kk);
                    const ulonglong2* hp =
                        reinterpret_cast<const ulonglong2*>(hb[il] + 4 * gru);
                    ulonglong2 h0 = hp[0], h1 = hp[1];
                    bacc[0] = fma2(wb2, h0.x, bacc[0]);
                    bacc[1] = fma2(wb2, h0.y, bacc[1]);
                    bacc[2] = fma2(wb2, h1.x, bacc[2]);
                    bacc[3] = fma2(wb2, h1.y, bacc[3]);
                }
                ISSUE_ONE();
            }
            ull bt[4];
#pragma unroll
            for (int c = 0; c < 4; ++c) {
                float2 v = unpack2(bacc[c]);
                bt[c] = pack2(tanhfast(fmaf(0.5f, v.x, bbk)),
                              tanhfast(fmaf(0.5f, v.y, bbk)));
                sh_betaP[4 * gru + c][k] = bt[c];
            }
            __syncthreads();   // BAR2: betaP + preA visible

            // ---- phase 3b: softmax scalars + e_chain ----
            if (t < 8) {
                float pa0 = sh_preA[2 * t], pa1 = sh_preA[2 * t + 1];
                float m0 = sh_m[2 * t], m1 = sh_m[2 * t + 1];
                float mn0 = fmaxf(m0, pa0), mn1 = fmaxf(m1, pa1);
                float sc0 = __expf(m0 - mn0), sc1 = __expf(m1 - mn1);
                float w0 = __expf(pa0 - mn0), w1 = __expf(pa1 - mn1);
                sh_l[2 * t] = sh_l[2 * t] * sc0 + w0;
                sh_l[2 * t + 1] = sh_l[2 * t + 1] * sc1 + w1;
                sh_m[2 * t] = mn0; sh_m[2 * t + 1] = mn1;
                sh_scaleP[t] = pack2(sc0, sc1);
                sh_wP[t] = pack2(w0, w1);
            }
            ull ea0 = 0ull, ea1 = 0ull;
            {
                const ull* bp0 = sh_betaP[q];
                const ull* bp1 = sh_betaP[q + 4];
                const float* wcp = sWo + (t & 63);
#pragma unroll 4
                for (int e = 0; e < 128; ++e) {
                    float wc = wcp[e * 64];
                    ull wc2 = pack2(wc, wc);
                    ea0 = fma2(wc2, bp0[e], ea0);
                    ea1 = fma2(wc2, bp1[e], ea1);
                }
            }
            __syncthreads();   // BAR3: scaleP/wP visible

            // ---- phase 3c: accumulators ----
            {
                const ull* ebp = g_embP + ((size_t)j * 32 + (b0 >> 1) + 4 * gru) * 128 + k;
#pragma unroll
                for (int c = 0; c < 4; ++c) {
                    int rp = 4 * gru + c;
                    ull prod = mul2(mul2(sh_wP[rp], bt[c]), ebp[(size_t)c * 128]);
                    cacc[c] = fma2(sh_scaleP[rp], cacc[c], prod);
                }
                const ull* xb = g_xP + ((size_t)j * 32 + (b0 >> 1) + q) * 64 + (t & 63);
                gacc[0] = fma2(sh_scaleP[q], gacc[0], mul2(mul2(sh_wP[q], ea0), xb[0]));
                gacc[1] = fma2(sh_scaleP[q + 4], gacc[1],
                               mul2(mul2(sh_wP[q + 4], ea1), xb[4 * 64]));
            }
        } // steps

        // ---- finalize ----
        __syncthreads();
        if (p >= base) {
            const int qi = p - base;
#pragma unroll
            for (int c = 0; c < 4; ++c) sh_betaP[4 * gru + c][k] = cacc[c];
            __syncthreads();

            if (t < 16) {
                float sum = 0.f;
                const ull* Crow = sh_betaP[t >> 1];
                const bool hi = (t & 1);
#pragma unroll 8
                for (int e = 0; e < 128; ++e) {
                    float2 v = unpack2(Crow[e]);
                    sum = fmaf(Wo[e], hi ? v.y : v.x, sum);
                }
                out[(size_t)(b0 + t) * nq + qi] = __fdividef(sum, sh_l[t]) + bo[0];
            }
            {
                float inv = __fdividef(1.f, (float)(p + 1));
                size_t wbase = (size_t)64 * nq;
#pragma unroll
                for (int cc = 0; cc < 2; ++cc) {
                    int rp = q + 4 * cc;
                    float2 gv = unpack2(gacc[cc]);
                    out[wbase + ((size_t)(b0 + 2 * rp) * nq + qi) * 64 + (t & 63)] =
                        __fdividef(gv.x, sh_l[2 * rp]) * inv;
                    out[wbase + ((size_t)(b0 + 2 * rp + 1) * nq + qi) * 64 + (t & 63)] =
                        __fdividef(gv.y, sh_l[2 * rp + 1]) * inv;
                }
            }
        }
        __syncthreads();
    } // segments
#undef WAITC
#undef ISSUE_ONE
}

// ---------------- launch ----------------
extern "C" void kernel_launch(void* const* d_in, const int* in_sizes, int n_in,
                              void* d_out, int out_size) {
    const float* x     = (const float*)d_in[0];
    const float* W_emb = (const float*)d_in[1];
    const float* b_emb = (const float*)d_in[2];
    const float* Wi_a  = (const float*)d_in[3];
    const float* Wh_a  = (const float*)d_in[4];
    const float* bi_a  = (const float*)d_in[5];
    const float* bh_a  = (const float*)d_in[6];
    const float* Wi_b  = (const float*)d_in[7];
    const float* Wh_b  = (const float*)d_in[8];
    const float* bi_b  = (const float*)d_in[9];
    const float* bh_b  = (const float*)d_in[10];
    const float* Wa    = (const float*)d_in[11];
    const float* ba    = (const float*)d_in[12];
    const float* Wb    = (const float*)d_in[13];
    const float* bb    = (const float*)d_in[14];
    const float* Wo    = (const float*)d_in[15];
    const float* bo    = (const float*)d_in[16];
    float* out = (float*)d_out;

    int nq = out_size / (64 * 65);

    static int smem_set = 0;
    if (!smem_set) {
        cudaFuncSetAttribute(retain_main,
                             cudaFuncAttributeMaxDynamicSharedMemorySize, SMEM_TOTAL);
        smem_set = 1;
    }

    prep_transpose<<<512, 256>>>(x, Wh_a, Wh_b, Wi_a, Wi_b, Wb, W_emb, Wo);
    emb_kernel<<<Tn * Bn, 128>>>(x, b_emb);
    gi_kernel<<<Tn * Bn, 256>>>(bi_a, bi_b);
    retain_main<<<128, 256, SMEM_TOTAL>>>(bh_a, bh_b, Wa, ba, bb, Wo, bo, nq, out);
}

// round 12
// speedup vs baseline: 1.2148x; 1.2148x over previous
#include <cuda_runtime.h>
#include <cstdint>

#define Bn 64
#define Tn 64
#define Dn 64
#define Pn 63
typedef unsigned long long ull;

// ---------------- device scratch ----------------
__device__ __align__(16) float g_emb[Tn * Bn * 128];         // [t][b][e]
__device__ __align__(16) ull   g_embP[Tn * 32 * 128];        // [t][rpg][e]
__device__ __align__(16) ull   g_giP[64 * 2 * 32 * 3 * 128]; // [t][gru][rpg][gate][k]
__device__ __align__(16) ull   g_xP[64 * 32 * 64];           // [j][bp][d]
__device__ __align__(16) float g_WiaT[128 * 384];            // [e][u]
__device__ __align__(16) float g_WibT[128 * 384];
// per-warp sliced Wh: [w 8][tile 8][li 16][ (wr,wz)x32kk | wn x32 ]
__device__ __align__(16) float g_WhW[8 * 8 * 16 * 96];
// band-sliced Wb: [band 4][tile 2][il 64][kk 32]
__device__ __align__(16) float g_WbW[4 * 2 * 64 * 32];
__device__ __align__(16) float g_WembT[64 * 128];            // [d][e]
__device__ __align__(16) float g_WoWemb[128 * 64];           // [e][d]

// ---------------- f32x2 helpers ----------------
__device__ __forceinline__ ull pack2(float x, float y) {
    ull r; asm("mov.b64 %0, {%1,%2};" : "=l"(r) : "f"(x), "f"(y)); return r;
}
__device__ __forceinline__ float2 unpack2(ull v) {
    float2 r; asm("mov.b64 {%0,%1}, %2;" : "=f"(r.x), "=f"(r.y) : "l"(v)); return r;
}
__device__ __forceinline__ ull fma2(ull a, ull b, ull c) {
    ull d; asm("fma.rn.f32x2 %0, %1, %2, %3;" : "=l"(d) : "l"(a), "l"(b), "l"(c)); return d;
}
__device__ __forceinline__ ull mul2(ull a, ull b) {
    ull d; asm("mul.rn.f32x2 %0, %1, %2;" : "=l"(d) : "l"(a), "l"(b)); return d;
}
__device__ __forceinline__ float sigmoidf_(float v) {
    return __fdividef(1.f, 1.f + __expf(-v));
}
__device__ __forceinline__ float tanhfast(float v) {
    float e = __expf(2.f * v);
    return 1.f - __fdividef(2.f, e + 1.f);
}
__device__ __forceinline__ float gru_step(float ir, float iz, float in_,
                                          float hr, float hz, float hn, float h) {
    float r = sigmoidf_(ir + hr);
    float z = sigmoidf_(iz + hz);
    float n = tanhfast(in_ + r * hn);
    return n + z * (h - n);
}

// ---------------- cp.async helpers ----------------
__device__ __forceinline__ void cp16(uint32_t dst, const void* src) {
    asm volatile("cp.async.cg.shared.global [%0], [%1], 16;\n" :: "r"(dst), "l"(src));
}
__device__ __forceinline__ void cp_commit() {
    asm volatile("cp.async.commit_group;\n" ::: "memory");
}
__device__ __forceinline__ void cp_wait1() {
    asm volatile("cp.async.wait_group 1;\n" ::: "memory");
}
__device__ __forceinline__ void cp_wait0() {
    asm volatile("cp.async.wait_group 0;\n" ::: "memory");
}

// ---------------- prep ----------------
__global__ void prep_transpose(const float* __restrict__ x,
                               const float* __restrict__ Wh_a,
                               const float* __restrict__ Wh_b,
                               const float* __restrict__ Wi_a,
                               const float* __restrict__ Wi_b,
                               const float* __restrict__ Wb,
                               const float* __restrict__ W_emb,
                               const float* __restrict__ Wo) {
    int idx = blockIdx.x * blockDim.x + threadIdx.x;
    int stride = gridDim.x * blockDim.x;
    for (int n = idx; n < 128 * 384; n += stride) {
        int u = n % 384, i = n / 384;
        g_WiaT[n] = Wi_a[u * 128 + i];
        g_WibT[n] = Wi_b[u * 128 + i];
    }
    for (int n = idx; n < 8 * 128 * 32; n += stride) {
        int w = n >> 12;
        int rem = n & 4095;
        int i = rem >> 5, kk = rem & 31;
        int gru = w >> 2, band = w & 3;
        int kq = band * 32 + kk;
        const float* Wh = gru ? Wh_b : Wh_a;
        float wr = Wh[kq * 128 + i];
        float wz = Wh[(128 + kq) * 128 + i];
        float wn = Wh[(256 + kq) * 128 + i];
        int tl = i >> 4, li = i & 15;
        int base = ((w * 8 + tl) * 16 + li) * 96;
        g_WhW[base + 2 * kk]     = wr;
        g_WhW[base + 2 * kk + 1] = wz;
        g_WhW[base + 64 + kk]    = wn;
    }
    for (int n = idx; n < 4 * 128 * 32; n += stride) {
        int band = n >> 12;
        int rem = n & 4095;
        int i = rem >> 5, kk = rem & 31;
        g_WbW[((band * 2 + (i >> 6)) * 64 + (i & 63)) * 32 + kk] =
            Wb[(band * 32 + kk) * 128 + i];
    }
    for (int n = idx; n < 64 * 128; n += stride) {
        int e = n % 128, d = n / 128;
        g_WembT[n] = W_emb[e * 64 + d];
    }
    for (int n = idx; n < 128 * 64; n += stride) {
        int d = n % 64, e = n / 64;
        g_WoWemb[n] = Wo[e] * W_emb[e * 64 + d];
    }
    for (int n = idx; n < 64 * 32 * 64; n += stride) {
        int j = n >> 11;
        int bp = (n >> 6) & 31;
        int d = n & 63;
        float x0 = x[((size_t)(2 * bp) * Tn + j) * Dn + d];
        float x1 = x[((size_t)(2 * bp + 1) * Tn + j) * Dn + d];
        g_xP[n] = pack2(x0, x1);
    }
}

// ---------------- emb ----------------
__global__ void emb_kernel(const float* __restrict__ x, const float* __restrict__ b_emb) {
    __shared__ float xs[64];
    int tb = blockIdx.x;
    int t_ = tb >> 6, b = tb & 63;
    int e = threadIdx.x;
    if (e < 64) xs[e] = x[((size_t)b * Tn + t_) * Dn + e];
    __syncthreads();
    float acc = 0.f;
#pragma unroll 8
    for (int d = 0; d < 64; ++d) acc = fmaf(g_WembT[d * 128 + e], xs[d], acc);
    g_emb[(size_t)tb * 128 + e] = acc + b_emb[e];
}

// ---------------- gi (packed) + emb packing ----------------
__global__ void gi_kernel(const float* __restrict__ bi_a, const float* __restrict__ bi_b) {
    __shared__ float es[128];
    int tb = blockIdx.x;
    int t_ = tb >> 6, b = tb & 63;
    int t = threadIdx.x;
    if (t < 128) es[t] = g_emb[(size_t)tb * 128 + t];
    __syncthreads();
    float* gf = (float*)g_giP;
    for (int u = t; u < 768; u += 256) {
        const float* WT;
        const float* bi;
        int gru, uu;
        if (u < 384) { WT = g_WiaT; bi = bi_a; gru = 0; uu = u; }
        else         { WT = g_WibT; bi = bi_b; gru = 1; uu = u - 384; }
        float acc = 0.f;
#pragma unroll 8
        for (int e = 0; e < 128; ++e) acc = fmaf(WT[e * 384 + uu], es[e], acc);
        int gate = uu >> 7, k = uu & 127;
        size_t ullIdx = (((size_t)(t_ * 2 + gru) * 32 + (b >> 1)) * 3 + gate) * 128 + k;
        gf[ullIdx * 2 + (b & 1)] = acc + bi[uu];
    }
    if ((b & 1) == 0 && t < 128) {
        g_embP[((size_t)t_ * 32 + (b >> 1)) * 128 + t] =
            pack2(g_emb[(size_t)tb * 128 + t], g_emb[(size_t)(tb + 1) * 128 + t]);
    }
}

// ---------------- main persistent kernel ----------------
// 256 threads, 8 warps. Per-warp 2-slot x 8KB rings; 10 tiles/step; 3 barriers/step.
#define RING_OFF   0                  // 8 warps x 2 slots x 8192 = 131072
#define SHH_OFF    131072             // ull [2][2][128][8] = 32768
#define BETA_OFF   163840             // ull [8][128] = 8192
#define WOW_OFF    172032             // float [128][64] = 32768
#define SCAL_OFF   204800             // scalars + Wa
#define SMEM_TOTAL 205824

__global__ __launch_bounds__(256, 1) void retain_main(
    const float* __restrict__ bh_a, const float* __restrict__ bh_b,
    const float* __restrict__ Wa, const float* __restrict__ ba,
    const float* __restrict__ bb, const float* __restrict__ Wo,
    const float* __restrict__ bo, int nq, float* __restrict__ out) {

    extern __shared__ char dsm[];
    float* smw = (float*)dsm;
    ull (*sh_h)[2][128][8] = (ull (*)[2][128][8])(dsm + SHH_OFF);
    ull (*sh_betaP)[128]   = (ull (*)[128])(dsm + BETA_OFF);
    float* sWo             = (float*)(dsm + WOW_OFF);
    float* sh_preA  = (float*)(dsm + SCAL_OFF);    // [16]
    float* sh_m     = sh_preA + 16;                // [16]
    float* sh_l     = sh_preA + 32;                // [16]
    ull*   sh_scaleP = (ull*)(sh_preA + 48);       // [8]
    ull*   sh_wP     = (ull*)(sh_preA + 64);       // [8]
    float* sh_Wa    = sh_preA + 80;                // [128]

    const int t = threadIdx.x;
    const int pb = blockIdx.x >> 2;
    const int chunkI = blockIdx.x & 3;
    const int b0 = chunkI * 16;

    const int w = t >> 5;
    const int lane = t & 31;
    const int gru = t >> 7;
    const int k = t & 127;
    const int band = w & 3;
    const int kk = lane;
    const int q = t >> 6;

    const float* bh = gru ? bh_b : bh_a;
    const float bhr = bh[k], bhz = bh[128 + k], bhn = bh[256 + k];
    const float ba0 = ba[0], bbk = bb[k];
    const int base = Pn - nq;

    for (int n = t; n < 8192; n += 256) sWo[n] = g_WoWemb[n];
    if (t < 128) sh_Wa[t] = Wa[t];

    const bool seg2 = (pb < 31) && (pb >= base);
    const int totalSteps = (63 - pb) + (seg2 ? pb + 1 : 0);
    const int totalTiles = 10 * totalSteps;

    uint32_t ringB = (uint32_t)__cvta_generic_to_shared(dsm) + (uint32_t)(w * 16384);
    int issIdx = 0, issM = 0, issSlot = 0, consSlot = 0;

#define ISSUE_ONE() do {                                                        \
        if (issIdx < totalTiles) {                                              \
            const char* _src; int _bytes;                                       \
            if (issM < 8) { _src = (const char*)g_WhW + (size_t)(w * 8 + issM) * 6144; _bytes = 6144; } \
            else { _src = (const char*)g_WbW + (size_t)(band * 2 + (issM - 8)) * 8192; _bytes = 8192; } \
            uint32_t _d = ringB + (uint32_t)(issSlot * 8192);                   \
            for (int _o = lane * 16; _o < _bytes; _o += 512) cp16(_d + _o, _src + _o); \
            cp_commit();                                                        \
            ++issIdx; if (++issM == 10) issM = 0; issSlot ^= 1;                 \
        }                                                                       \
    } while (0)

#define WAITC() do {                                                            \
        if (issIdx < totalTiles) cp_wait1(); else cp_wait0();                   \
        __syncwarp();                                                           \
    } while (0)

    ISSUE_ONE();
    ISSUE_ONE();

    for (int seg = 0; seg < 2; ++seg) {
        const int p = seg ? pb : 62 - pb;
        if (seg && !seg2) break;

        for (int n = t; n < 2 * 128 * 8; n += 256)
            ((ull*)sh_h[0])[n] = 0ull;
        if (t < 16) { sh_m[t] = -1e30f; sh_l[t] = 0.f; }
        ull cacc[4] = {0ull, 0ull, 0ull, 0ull};
        ull gacc[2] = {0ull, 0ull};
        __syncthreads();

        for (int s = 0; s <= p; ++s) {
            const int j = p - s;
            const int cb = s & 1;
            const ull (*cur)[8]  = sh_h[cb][gru];
            ull (*nxtg)[8]       = sh_h[cb ^ 1][gru];
            const ull (*nxtA)[8] = sh_h[cb ^ 1][0];
            const ull (*nxtB)[8] = sh_h[cb ^ 1][1];

            // ---- prefetch gi for this step into registers (latency covered by phase 1) ----
            ull gbuf[24];
            {
                const ull* gb = g_giP + (((size_t)(j * 2 + gru) * 32 + (b0 >> 1)) * 3) * 128 + k;
#pragma unroll
                for (int r = 0; r < 8; ++r) {
                    gbuf[r * 3]     = gb[(size_t)r * 384];
                    gbuf[r * 3 + 1] = gb[(size_t)r * 384 + 128];
                    gbuf[r * 3 + 2] = gb[(size_t)r * 384 + 256];
                }
            }

            // ---- phase 1: gh = h @ Wh^T, 8 row-pairs, self-paced weight tiles ----
            ull aR[8], aZ[8], aN[8];
#pragma unroll
            for (int r = 0; r < 8; ++r) { aR[r] = 0ull; aZ[r] = 0ull; aN[r] = 0ull; }

#pragma unroll 1
            for (int tl = 0; tl < 8; ++tl) {
                WAITC();
                const float* wp = smw + w * 4096 + consSlot * 2048;
                consSlot ^= 1;
                const ull (*hrow)[8] = &cur[tl * 16];
#pragma unroll
                for (int li = 0; li < 16; ++li) {
                    float2 rz = *(const float2*)(wp + li * 96 + 2 * kk);
                    float wn = wp[li * 96 + 64 + kk];
                    ull wr2 = pack2(rz.x, rz.x), wz2 = pack2(rz.y, rz.y), wn2 = pack2(wn, wn);
                    const ulonglong2* hp = reinterpret_cast<const ulonglong2*>(hrow[li]);
                    ulonglong2 hA = hp[0], hB = hp[1], hC = hp[2], hD = hp[3];
                    aR[0] = fma2(wr2, hA.x, aR[0]); aZ[0] = fma2(wz2, hA.x, aZ[0]); aN[0] = fma2(wn2, hA.x, aN[0]);
                    aR[1] = fma2(wr2, hA.y, aR[1]); aZ[1] = fma2(wz2, hA.y, aZ[1]); aN[1] = fma2(wn2, hA.y, aN[1]);
                    aR[2] = fma2(wr2, hB.x, aR[2]); aZ[2] = fma2(wz2, hB.x, aZ[2]); aN[2] = fma2(wn2, hB.x, aN[2]);
                    aR[3] = fma2(wr2, hB.y, aR[3]); aZ[3] = fma2(wz2, hB.y, aZ[3]); aN[3] = fma2(wn2, hB.y, aN[3]);
                    aR[4] = fma2(wr2, hC.x, aR[4]); aZ[4] = fma2(wz2, hC.x, aZ[4]); aN[4] = fma2(wn2, hC.x, aN[4]);
                    aR[5] = fma2(wr2, hC.y, aR[5]); aZ[5] = fma2(wz2, hC.y, aZ[5]); aN[5] = fma2(wn2, hC.y, aN[5]);
                    aR[6] = fma2(wr2, hD.x, aR[6]); aZ[6] = fma2(wz2, hD.x, aZ[6]); aN[6] = fma2(wn2, hD.x, aN[6]);
                    aR[7] = fma2(wr2, hD.y, aR[7]); aZ[7] = fma2(wz2, hD.y, aZ[7]); aN[7] = fma2(wn2, hD.y, aN[7]);
                }
                ISSUE_ONE();
            }

            // ---- phase 2: GRU update for 8 row-pairs at hidden k (gi from regs) ----
            {
#pragma unroll
                for (int r = 0; r < 8; ++r) {
                    float2 gr = unpack2(gbuf[r * 3]);
                    float2 gz = unpack2(gbuf[r * 3 + 1]);
                    float2 gn = unpack2(gbuf[r * 3 + 2]);
                    float2 hr = unpack2(aR[r]);
                    float2 hz = unpack2(aZ[r]);
                    float2 hn = unpack2(aN[r]);
                    float2 ho = unpack2(cur[k][r]);
                    float hx = gru_step(gr.x, gz.x, gn.x,
                                        hr.x + bhr, hz.x + bhz, hn.x + bhn, ho.x);
                    float hy = gru_step(gr.y, gz.y, gn.y,
                                        hr.y + bhr, hz.y + bhz, hn.y + bhn, ho.y);
                    nxtg[k][r] = pack2(hx, hy);
                }
            }
            __syncthreads();   // BAR1: h visible

            // ---- preA first (overlaps first Wb tile landing; R10-proven) ----
            {
#pragma unroll
                for (int rr = 0; rr < 2; ++rr) {
                    int r = w + 8 * rr;
                    float part = 0.f;
#pragma unroll
                    for (int ii = 0; ii < 4; ++ii) {
                        int i = lane + 32 * ii;
                        float2 hv = unpack2(nxtA[i][r >> 1]);
                        part = fmaf(sh_Wa[i], (r & 1) ? hv.y : hv.x, part);
                    }
#pragma unroll
                    for (int o = 16; o; o >>= 1)
                        part += __shfl_xor_sync(0xffffffffu, part, o);
                    if (lane == 0) sh_preA[r] = fmaf(0.5f, part, ba0);
                }
            }

            // ---- phase 3a: beta (rps 4gru..4gru+3, full i) ----
            ull bacc[4] = {0ull, 0ull, 0ull, 0ull};
#pragma unroll 1
            for (int tb = 0; tb < 2; ++tb) {
                WAITC();
                const float* wbp = smw + w * 4096 + consSlot * 2048;
                consSlot ^= 1;
                const ull (*hb)[8] = &nxtB[tb * 64];
#pragma unroll 4
                for (int il = 0; il < 64; ++il) {
                    float wv = wbp[il * 32 + kk];
                    ull wb2 = pack2(wv, wv);
                    const ulonglong2* hp =
                        reinterpret_cast<const ulonglong2*>(hb[il] + 4 * gru);
                    ulonglong2 h0 = hp[0], h1 = hp[1];
                    bacc[0] = fma2(wb2, h0.x, bacc[0]);
                    bacc[1] = fma2(wb2, h0.y, bacc[1]);
                    bacc[2] = fma2(wb2, h1.x, bacc[2]);
                    bacc[3] = fma2(wb2, h1.y, bacc[3]);
                }
                ISSUE_ONE();
            }
            ull bt[4];
#pragma unroll
            for (int c = 0; c < 4; ++c) {
                float2 v = unpack2(bacc[c]);
                bt[c] = pack2(tanhfast(fmaf(0.5f, v.x, bbk)),
                              tanhfast(fmaf(0.5f, v.y, bbk)));
                sh_betaP[4 * gru + c][k] = bt[c];
            }
            __syncthreads();   // BAR2: betaP + preA visible

            // ---- prefetch embP/xP for 3c (latency covered by e_chain) ----
            ull ebr[4], xr0, xr1;
            {
                const ull* ebp = g_embP + ((size_t)j * 32 + (b0 >> 1) + 4 * gru) * 128 + k;
#pragma unroll
                for (int c = 0; c < 4; ++c) ebr[c] = ebp[(size_t)c * 128];
                const ull* xb = g_xP + ((size_t)j * 32 + (b0 >> 1) + q) * 64 + (t & 63);
                xr0 = xb[0];
                xr1 = xb[4 * 64];
            }

            // ---- phase 3b: softmax scalars + e_chain ----
            if (t < 8) {
                float pa0 = sh_preA[2 * t], pa1 = sh_preA[2 * t + 1];
                float m0 = sh_m[2 * t], m1 = sh_m[2 * t + 1];
                float mn0 = fmaxf(m0, pa0), mn1 = fmaxf(m1, pa1);
                float sc0 = __expf(m0 - mn0), sc1 = __expf(m1 - mn1);
                float w0 = __expf(pa0 - mn0), w1 = __expf(pa1 - mn1);
                sh_l[2 * t] = sh_l[2 * t] * sc0 + w0;
                sh_l[2 * t + 1] = sh_l[2 * t + 1] * sc1 + w1;
                sh_m[2 * t] = mn0; sh_m[2 * t + 1] = mn1;
                sh_scaleP[t] = pack2(sc0, sc1);
                sh_wP[t] = pack2(w0, w1);
            }
            ull ea0 = 0ull, ea1 = 0ull;
            {
                const ull* bp0 = sh_betaP[q];
                const ull* bp1 = sh_betaP[q + 4];
                const float* wcp = sWo + (t & 63);
#pragma unroll 4
                for (int e = 0; e < 128; ++e) {
                    float wc = wcp[e * 64];
                    ull wc2 = pack2(wc, wc);
                    ea0 = fma2(wc2, bp0[e], ea0);
                    ea1 = fma2(wc2, bp1[e], ea1);
                }
            }
            __syncthreads();   // BAR3: scaleP/wP visible

            // ---- phase 3c: accumulators (registers only) ----
            {
#pragma unroll
                for (int c = 0; c < 4; ++c) {
                    int rp = 4 * gru + c;
                    ull prod = mul2(mul2(sh_wP[rp], bt[c]), ebr[c]);
                    cacc[c] = fma2(sh_scaleP[rp], cacc[c], prod);
                }
                gacc[0] = fma2(sh_scaleP[q], gacc[0], mul2(mul2(sh_wP[q], ea0), xr0));
                gacc[1] = fma2(sh_scaleP[q + 4], gacc[1],
                               mul2(mul2(sh_wP[q + 4], ea1), xr1));
            }
        } // steps

        // ---- finalize ----
        __syncthreads();
        if (p >= base) {
            const int qi = p - base;
#pragma unroll
            for (int c = 0; c < 4; ++c) sh_betaP[4 * gru + c][k] = cacc[c];
            __syncthreads();

            if (t < 16) {
                float sum = 0.f;
                const ull* Crow = sh_betaP[t >> 1];
                const bool hi = (t & 1);
#pragma unroll 8
                for (int e = 0; e < 128; ++e) {
                    float2 v = unpack2(Crow[e]);
                    sum = fmaf(Wo[e], hi ? v.y : v.x, sum);
                }
                out[(size_t)(b0 + t) * nq + qi] = __fdividef(sum, sh_l[t]) + bo[0];
            }
            {
                float inv = __fdividef(1.f, (float)(p + 1));
                size_t wbase = (size_t)64 * nq;
#pragma unroll
                for (int cc = 0; cc < 2; ++cc) {
                    int rp = q + 4 * cc;
                    float2 gv = unpack2(gacc[cc]);
                    out[wbase + ((size_t)(b0 + 2 * rp) * nq + qi) * 64 + (t & 63)] =
                        __fdividef(gv.x, sh_l[2 * rp]) * inv;
                    out[wbase + ((size_t)(b0 + 2 * rp + 1) * nq + qi) * 64 + (t & 63)] =
                        __fdividef(gv.y, sh_l[2 * rp + 1]) * inv;
                }
            }
        }
        __syncthreads();
    } // segments
#undef WAITC
#undef ISSUE_ONE
}

// ---------------- launch ----------------
extern "C" void kernel_launch(void* const* d_in, const int* in_sizes, int n_in,
                              void* d_out, int out_size) {
    const float* x     = (const float*)d_in[0];
    const float* W_emb = (const float*)d_in[1];
    const float* b_emb = (const float*)d_in[2];
    const float* Wi_a  = (const float*)d_in[3];
    const float* Wh_a  = (const float*)d_in[4];
    const float* bi_a  = (const float*)d_in[5];
    const float* bh_a  = (const float*)d_in[6];
    const float* Wi_b  = (const float*)d_in[7];
    const float* Wh_b  = (const float*)d_in[8];
    const float* bi_b  = (const float*)d_in[9];
    const float* bh_b  = (const float*)d_in[10];
    const float* Wa    = (const float*)d_in[11];
    const float* ba    = (const float*)d_in[12];
    const float* Wb    = (const float*)d_in[13];
    const float* bb    = (const float*)d_in[14];
    const float* Wo    = (const float*)d_in[15];
    const float* bo    = (const float*)d_in[16];
    float* out = (float*)d_out;

    int nq = out_size / (64 * 65);

    static int smem_set = 0;
    if (!smem_set) {
        cudaFuncSetAttribute(retain_main,
                             cudaFuncAttributeMaxDynamicSharedMemorySize, SMEM_TOTAL);
        smem_set = 1;
    }

    prep_transpose<<<256, 256>>>(x, Wh_a, Wh_b, Wi_a, Wi_b, Wb, W_emb, Wo);
    emb_kernel<<<Tn * Bn, 128>>>(x, b_emb);
    gi_kernel<<<Tn * Bn, 256>>>(bi_a, bi_b);
    retain_main<<<128, 256, SMEM_TOTAL>>>(bh_a, bh_b, Wa, ba, bb, Wo, bo, nq, out);
}

// round 13
// speedup vs baseline: 1.3460x; 1.1080x over previous
#include <cuda_runtime.h>
#include <cstdint>

#define Bn 64
#define Tn 64
#define Dn 64
#define Pn 63
typedef unsigned long long ull;

// ---------------- device scratch ----------------
__device__ __align__(16) float g_emb[Tn * Bn * 128];         // [t][b][e]
__device__ __align__(16) ull   g_embP[Tn * 32 * 128];        // [t][rpg][e]
__device__ __align__(16) ull   g_giP[64 * 2 * 32 * 3 * 128]; // [t][gru][rpg][gate][k]
__device__ __align__(16) ull   g_xP[64 * 32 * 64];           // [j][bp][d]
__device__ __align__(16) float g_WiaT[128 * 384];            // [e][u]
__device__ __align__(16) float g_WibT[128 * 384];
// combined per-warp tiles: [w 8][tile 8][ Wh: li16 x 96 | Wb: li16 x 32 ] = 2048 floats (8KB)
__device__ __align__(16) float g_WC[8 * 8 * 2048];
__device__ __align__(16) float g_WembT[64 * 128];            // [d][e]
__device__ __align__(16) float g_WoWemb[128 * 64];           // [e][d]

// ---------------- f32x2 helpers ----------------
__device__ __forceinline__ ull pack2(float x, float y) {
    ull r; asm("mov.b64 %0, {%1,%2};" : "=l"(r) : "f"(x), "f"(y)); return r;
}
__device__ __forceinline__ float2 unpack2(ull v) {
    float2 r; asm("mov.b64 {%0,%1}, %2;" : "=f"(r.x), "=f"(r.y) : "l"(v)); return r;
}
__device__ __forceinline__ ull fma2(ull a, ull b, ull c) {
    ull d; asm("fma.rn.f32x2 %0, %1, %2, %3;" : "=l"(d) : "l"(a), "l"(b), "l"(c)); return d;
}
__device__ __forceinline__ ull mul2(ull a, ull b) {
    ull d; asm("mul.rn.f32x2 %0, %1, %2;" : "=l"(d) : "l"(a), "l"(b)); return d;
}
__device__ __forceinline__ float sigmoidf_(float v) {
    return __fdividef(1.f, 1.f + __expf(-v));
}
__device__ __forceinline__ float tanhfast(float v) {
    float e = __expf(2.f * v);
    return 1.f - __fdividef(2.f, e + 1.f);
}
__device__ __forceinline__ float gru_step(float ir, float iz, float in_,
                                          float hr, float hz, float hn, float h) {
    float r = sigmoidf_(ir + hr);
    float z = sigmoidf_(iz + hz);
    float n = tanhfast(in_ + r * hn);
    return n + z * (h - n);
}

// ---------------- cp.async helpers ----------------
__device__ __forceinline__ void cp16(uint32_t dst, const void* src) {
    asm volatile("cp.async.cg.shared.global [%0], [%1], 16;\n" :: "r"(dst), "l"(src));
}
__device__ __forceinline__ void cp_commit() {
    asm volatile("cp.async.commit_group;\n" ::: "memory");
}
__device__ __forceinline__ void cp_wait1() {
    asm volatile("cp.async.wait_group 1;\n" ::: "memory");
}
__device__ __forceinline__ void cp_wait0() {
    asm volatile("cp.async.wait_group 0;\n" ::: "memory");
}

// ---------------- prep ----------------
__global__ void prep_transpose(const float* __restrict__ x,
                               const float* __restrict__ Wh_a,
                               const float* __restrict__ Wh_b,
                               const float* __restrict__ Wi_a,
                               const float* __restrict__ Wi_b,
                               const float* __restrict__ Wb,
                               const float* __restrict__ W_emb,
                               const float* __restrict__ Wo) {
    int idx = blockIdx.x * blockDim.x + threadIdx.x;
    int stride = gridDim.x * blockDim.x;
    for (int n = idx; n < 128 * 384; n += stride) {
        int u = n % 384, i = n / 384;
        g_WiaT[n] = Wi_a[u * 128 + i];
        g_WibT[n] = Wi_b[u * 128 + i];
    }
    // Wh part of combined tiles
    for (int n = idx; n < 8 * 128 * 32; n += stride) {
        int w = n >> 12;
        int rem = n & 4095;
        int i = rem >> 5, kk = rem & 31;
        int gru = w >> 2, band = w & 3;
        int kq = band * 32 + kk;
        const float* Wh = gru ? Wh_b : Wh_a;
        float wr = Wh[kq * 128 + i];
        float wz = Wh[(128 + kq) * 128 + i];
        float wn = Wh[(256 + kq) * 128 + i];
        int tl = i >> 4, li = i & 15;
        int bas = (w * 8 + tl) * 2048 + li * 96;
        g_WC[bas + 2 * kk]     = wr;
        g_WC[bas + 2 * kk + 1] = wz;
        g_WC[bas + 64 + kk]    = wn;
    }
    // Wb part of combined tiles (duplicated across gru halves)
    for (int n = idx; n < 8 * 128 * 32; n += stride) {
        int w = n >> 12;
        int rem = n & 4095;
        int i = rem >> 5, kk = rem & 31;
        int band = w & 3;
        int tl = i >> 4, li = i & 15;
        g_WC[(w * 8 + tl) * 2048 + 1536 + li * 32 + kk] =
            Wb[(band * 32 + kk) * 128 + i];
    }
    for (int n = idx; n < 64 * 128; n += stride) {
        int e = n % 128, d = n / 128;
        g_WembT[n] = W_emb[e * 64 + d];
    }
    for (int n = idx; n < 128 * 64; n += stride) {
        int d = n % 64, e = n / 64;
        g_WoWemb[n] = Wo[e] * W_emb[e * 64 + d];
    }
    for (int n = idx; n < 64 * 32 * 64; n += stride) {
        int j = n >> 11;
        int bp = (n >> 6) & 31;
        int d = n & 63;
        float x0 = x[((size_t)(2 * bp) * Tn + j) * Dn + d];
        float x1 = x[((size_t)(2 * bp + 1) * Tn + j) * Dn + d];
        g_xP[n] = pack2(x0, x1);
    }
}

// ---------------- emb ----------------
__global__ void emb_kernel(const float* __restrict__ x, const float* __restrict__ b_emb) {
    __shared__ float xs[64];
    int tb = blockIdx.x;
    int t_ = tb >> 6, b = tb & 63;
    int e = threadIdx.x;
    if (e < 64) xs[e] = x[((size_t)b * Tn + t_) * Dn + e];
    __syncthreads();
    float acc = 0.f;
#pragma unroll 8
    for (int d = 0; d < 64; ++d) acc = fmaf(g_WembT[d * 128 + e], xs[d], acc);
    g_emb[(size_t)tb * 128 + e] = acc + b_emb[e];
}

// ---------------- gi (packed) + emb packing ----------------
__global__ void gi_kernel(const float* __restrict__ bi_a, const float* __restrict__ bi_b) {
    __shared__ float es[128];
    int tb = blockIdx.x;
    int t_ = tb >> 6, b = tb & 63;
    int t = threadIdx.x;
    if (t < 128) es[t] = g_emb[(size_t)tb * 128 + t];
    __syncthreads();
    float* gf = (float*)g_giP;
    for (int u = t; u < 768; u += 256) {
        const float* WT;
        const float* bi;
        int gru, uu;
        if (u < 384) { WT = g_WiaT; bi = bi_a; gru = 0; uu = u; }
        else         { WT = g_WibT; bi = bi_b; gru = 1; uu = u - 384; }
        float acc = 0.f;
#pragma unroll 8
        for (int e = 0; e < 128; ++e) acc = fmaf(WT[e * 384 + uu], es[e], acc);
        int gate = uu >> 7, k = uu & 127;
        size_t ullIdx = (((size_t)(t_ * 2 + gru) * 32 + (b >> 1)) * 3 + gate) * 128 + k;
        gf[ullIdx * 2 + (b & 1)] = acc + bi[uu];
    }
    if ((b & 1) == 0 && t < 128) {
        g_embP[((size_t)t_ * 32 + (b >> 1)) * 128 + t] =
            pack2(g_emb[(size_t)tb * 128 + t], g_emb[(size_t)(tb + 1) * 128 + t]);
    }
}

// ---------------- main persistent kernel ----------------
// 256 threads, 8 warps. Per-warp 2-slot x 8KB rings of COMBINED (Wh|Wb) tiles.
// Pipelined: fused loop computes next-step gh + this-step beta together.
#define RING_OFF   0                  // 8 warps x 2 slots x 8192 = 131072
#define SHH_OFF    131072             // ull [2][2][128][8] = 32768
#define BETA_OFF   163840             // ull [8][128] = 8192
#define WOW_OFF    172032             // float [128][64] = 32768
#define SCAL_OFF   204800             // scalars + Wa
#define SMEM_TOTAL 205824

__global__ __launch_bounds__(256, 1) void retain_main(
    const float* __restrict__ bh_a, const float* __restrict__ bh_b,
    const float* __restrict__ Wa, const float* __restrict__ ba,
    const float* __restrict__ bb, const float* __restrict__ Wo,
    const float* __restrict__ bo, int nq, float* __restrict__ out) {

    extern __shared__ char dsm[];
    float* smw = (float*)dsm;
    ull (*sh_h)[2][128][8] = (ull (*)[2][128][8])(dsm + SHH_OFF);
    ull (*sh_betaP)[128]   = (ull (*)[128])(dsm + BETA_OFF);
    float* sWo             = (float*)(dsm + WOW_OFF);
    float* sh_preA  = (float*)(dsm + SCAL_OFF);    // [16]
    float* sh_m     = sh_preA + 16;                // [16]
    float* sh_l     = sh_preA + 32;                // [16]
    ull*   sh_scaleP = (ull*)(sh_preA + 48);       // [8]
    ull*   sh_wP     = (ull*)(sh_preA + 64);       // [8]
    float* sh_Wa    = sh_preA + 80;                // [128]

    const int t = threadIdx.x;
    const int pb = blockIdx.x >> 2;
    const int chunkI = blockIdx.x & 3;
    const int b0 = chunkI * 16;

    const int w = t >> 5;
    const int lane = t & 31;
    const int gru = t >> 7;
    const int k = t & 127;
    const int kk = lane;
    const int q = t >> 6;

    const float* bh = gru ? bh_b : bh_a;
    const float bhr = bh[k], bhz = bh[128 + k], bhn = bh[256 + k];
    const float ba0 = ba[0], bbk = bb[k];
    const int base = Pn - nq;

    for (int n = t; n < 8192; n += 256) sWo[n] = g_WoWemb[n];
    if (t < 128) sh_Wa[t] = Wa[t];

    const bool seg2 = (pb < 31) && (pb >= base);
    const int totalSteps = (63 - pb) + (seg2 ? pb + 1 : 0);
    const int totalTiles = 8 * totalSteps;

    uint32_t ringB = (uint32_t)__cvta_generic_to_shared(dsm) + (uint32_t)(w * 16384);
    int issIdx = 0, issM = 0, issSlot = 0, consSlot = 0;

#define ISSUE_ONE() do {                                                        \
        if (issIdx < totalTiles) {                                              \
            const char* _src = (const char*)g_WC + ((size_t)(w * 8 + issM)) * 8192; \
            uint32_t _d = ringB + (uint32_t)(issSlot * 8192);                   \
            for (int _o = lane * 16; _o < 8192; _o += 512) cp16(_d + _o, _src + _o); \
            cp_commit();                                                        \
            ++issIdx; if (++issM == 8) issM = 0; issSlot ^= 1;                  \
        }                                                                       \
    } while (0)

#define WAITC() do {                                                            \
        if (issIdx < totalTiles) cp_wait1(); else cp_wait0();                   \
        __syncwarp();                                                           \
    } while (0)

    ISSUE_ONE();
    ISSUE_ONE();

    ull aR[8], aZ[8], aN[8];   // gh accumulators, pipelined across steps
    ull gbuf[24];              // gi for the current step

    for (int seg = 0; seg < 2; ++seg) {
        const int p = seg ? pb : 62 - pb;
        if (seg && !seg2) break;

        for (int n = t; n < 2 * 128 * 8; n += 256)
            ((ull*)sh_h[0])[n] = 0ull;
        if (t < 16) { sh_m[t] = -1e30f; sh_l[t] = 0.f; }
        ull cacc[4] = {0ull, 0ull, 0ull, 0ull};
        ull gacc[2] = {0ull, 0ull};
        // h(0)=0 -> gh(0)=0
#pragma unroll
        for (int r = 0; r < 8; ++r) { aR[r] = 0ull; aZ[r] = 0ull; aN[r] = 0ull; }
        // prefetch gi for step 0 (j = p)
        {
            const ull* gb = g_giP + (((size_t)(p * 2 + gru) * 32 + (b0 >> 1)) * 3) * 128 + k;
#pragma unroll
            for (int r = 0; r < 8; ++r) {
                gbuf[r * 3]     = gb[(size_t)r * 384];
                gbuf[r * 3 + 1] = gb[(size_t)r * 384 + 128];
                gbuf[r * 3 + 2] = gb[(size_t)r * 384 + 256];
            }
        }
        __syncthreads();

        for (int s = 0; s <= p; ++s) {
            const int j = p - s;
            const int cb = s & 1;
            const ull (*cur)[8]  = sh_h[cb][gru];
            ull (*nxtg)[8]       = sh_h[cb ^ 1][gru];
            const ull (*nxtA)[8] = sh_h[cb ^ 1][0];
            const ull (*nxtB)[8] = sh_h[cb ^ 1][1];

            // ---- phase 2: GRU update for 8 row-pairs at hidden k (aX from pipeline) ----
            {
#pragma unroll
                for (int r = 0; r < 8; ++r) {
                    float2 gr = unpack2(gbuf[r * 3]);
                    float2 gz = unpack2(gbuf[r * 3 + 1]);
                    float2 gn = unpack2(gbuf[r * 3 + 2]);
                    float2 hr = unpack2(aR[r]);
                    float2 hz = unpack2(aZ[r]);
                    float2 hn = unpack2(aN[r]);
                    float2 ho = unpack2(cur[k][r]);
                    float hx = gru_step(gr.x, gz.x, gn.x,
                                        hr.x + bhr, hz.x + bhz, hn.x + bhn, ho.x);
                    float hy = gru_step(gr.y, gz.y, gn.y,
                                        hr.y + bhr, hz.y + bhz, hn.y + bhn, ho.y);
                    nxtg[k][r] = pack2(hx, hy);
                }
            }
            __syncthreads();   // BAR1: h(s+1) visible

            // ---- prefetch gi for step s+1 (covered by fused loop) ----
            {
                int jn = (j > 0) ? j - 1 : 0;
                const ull* gb = g_giP + (((size_t)(jn * 2 + gru) * 32 + (b0 >> 1)) * 3) * 128 + k;
#pragma unroll
                for (int r = 0; r < 8; ++r) {
                    gbuf[r * 3]     = gb[(size_t)r * 384];
                    gbuf[r * 3 + 1] = gb[(size_t)r * 384 + 128];
                    gbuf[r * 3 + 2] = gb[(size_t)r * 384 + 256];
                }
            }

            // ---- preA(s) on the new h ----
            {
#pragma unroll
                for (int rr = 0; rr < 2; ++rr) {
                    int r = w + 8 * rr;
                    float part = 0.f;
#pragma unroll
                    for (int ii = 0; ii < 4; ++ii) {
                        int i = lane + 32 * ii;
                        float2 hv = unpack2(nxtA[i][r >> 1]);
                        part = fmaf(sh_Wa[i], (r & 1) ? hv.y : hv.x, part);
                    }
#pragma unroll
                    for (int o = 16; o; o >>= 1)
                        part += __shfl_xor_sync(0xffffffffu, part, o);
                    if (lane == 0) sh_preA[r] = fmaf(0.5f, part, ba0);
                }
            }

            // ---- FUSED: gh(s+1) (24 fma2) + beta(s) (4 fma2) over i = 0..127 ----
#pragma unroll
            for (int r = 0; r < 8; ++r) { aR[r] = 0ull; aZ[r] = 0ull; aN[r] = 0ull; }
            ull bacc[4] = {0ull, 0ull, 0ull, 0ull};
#pragma unroll 1
            for (int tl = 0; tl < 8; ++tl) {
                WAITC();
                const float* wp = smw + w * 4096 + consSlot * 2048;
                consSlot ^= 1;
                const ull (*hrow)[8]  = (const ull (*)[8])&nxtg[tl * 16]; // my gru h(s+1)
                const ull (*hrowB)[8] = &nxtB[tl * 16];                   // GRU-b h(s+1)
#pragma unroll
                for (int li = 0; li < 16; ++li) {
                    float2 rz = *(const float2*)(wp + li * 96 + 2 * kk);
                    float wnv = wp[li * 96 + 64 + kk];
                    float wbv = wp[1536 + li * 32 + kk];
                    ull wr2 = pack2(rz.x, rz.x), wz2 = pack2(rz.y, rz.y);
                    ull wn2 = pack2(wnv, wnv), wb2 = pack2(wbv, wbv);
                    const ulonglong2* hp = reinterpret_cast<const ulonglong2*>(hrow[li]);
                    ulonglong2 hA = hp[0], hB = hp[1], hC = hp[2], hD = hp[3];
                    const ulonglong2* hq =
                        reinterpret_cast<const ulonglong2*>(hrowB[li] + 4 * gru);
                    ulonglong2 b0v = hq[0], b1v = hq[1];
                    aR[0] = fma2(wr2, hA.x, aR[0]); aZ[0] = fma2(wz2, hA.x, aZ[0]); aN[0] = fma2(wn2, hA.x, aN[0]);
                    bacc[0] = fma2(wb2, b0v.x, bacc[0]);
                    aR[1] = fma2(wr2, hA.y, aR[1]); aZ[1] = fma2(wz2, hA.y, aZ[1]); aN[1] = fma2(wn2, hA.y, aN[1]);
                    bacc[1] = fma2(wb2, b0v.y, bacc[1]);
                    aR[2] = fma2(wr2, hB.x, aR[2]); aZ[2] = fma2(wz2, hB.x, aZ[2]); aN[2] = fma2(wn2, hB.x, aN[2]);
                    bacc[2] = fma2(wb2, b1v.x, bacc[2]);
                    aR[3] = fma2(wr2, hB.y, aR[3]); aZ[3] = fma2(wz2, hB.y, aZ[3]); aN[3] = fma2(wn2, hB.y, aN[3]);
                    bacc[3] = fma2(wb2, b1v.y, bacc[3]);
                    aR[4] = fma2(wr2, hC.x, aR[4]); aZ[4] = fma2(wz2, hC.x, aZ[4]); aN[4] = fma2(wn2, hC.x, aN[4]);
                    aR[5] = fma2(wr2, hC.y, aR[5]); aZ[5] = fma2(wz2, hC.y, aZ[5]); aN[5] = fma2(wn2, hC.y, aN[5]);
                    aR[6] = fma2(wr2, hD.x, aR[6]); aZ[6] = fma2(wz2, hD.x, aZ[6]); aN[6] = fma2(wn2, hD.x, aN[6]);
                    aR[7] = fma2(wr2, hD.y, aR[7]); aZ[7] = fma2(wz2, hD.y, aZ[7]); aN[7] = fma2(wn2, hD.y, aN[7]);
                }
                ISSUE_ONE();
            }

            ull bt[4];
#pragma unroll
            for (int c = 0; c < 4; ++c) {
                float2 v = unpack2(bacc[c]);
                bt[c] = pack2(tanhfast(fmaf(0.5f, v.x, bbk)),
                              tanhfast(fmaf(0.5f, v.y, bbk)));
                sh_betaP[4 * gru + c][k] = bt[c];
            }
            __syncthreads();   // BAR2: betaP + preA visible

            // ---- prefetch embP/xP for 3c (covered by e_chain) ----
            ull ebr[4], xr0, xr1;
            {
                const ull* ebp = g_embP + ((size_t)j * 32 + (b0 >> 1) + 4 * gru) * 128 + k;
#pragma unroll
                for (int c = 0; c < 4; ++c) ebr[c] = ebp[(size_t)c * 128];
                const ull* xb = g_xP + ((size_t)j * 32 + (b0 >> 1) + q) * 64 + (t & 63);
                xr0 = xb[0];
                xr1 = xb[4 * 64];
            }

            // ---- softmax scalars + e_chain ----
            if (t < 8) {
                float pa0 = sh_preA[2 * t], pa1 = sh_preA[2 * t + 1];
                float m0 = sh_m[2 * t], m1 = sh_m[2 * t + 1];
                float mn0 = fmaxf(m0, pa0), mn1 = fmaxf(m1, pa1);
                float sc0 = __expf(m0 - mn0), sc1 = __expf(m1 - mn1);
                float w0 = __expf(pa0 - mn0), w1 = __expf(pa1 - mn1);
                sh_l[2 * t] = sh_l[2 * t] * sc0 + w0;
                sh_l[2 * t + 1] = sh_l[2 * t + 1] * sc1 + w1;
                sh_m[2 * t] = mn0; sh_m[2 * t + 1] = mn1;
                sh_scaleP[t] = pack2(sc0, sc1);
                sh_wP[t] = pack2(w0, w1);
            }
            ull ea0 = 0ull, ea1 = 0ull;
            {
                const ull* bp0 = sh_betaP[q];
                const ull* bp1 = sh_betaP[q + 4];
                const float* wcp = sWo + (t & 63);
#pragma unroll 4
                for (int e = 0; e < 128; ++e) {
                    float wc = wcp[e * 64];
                    ull wc2 = pack2(wc, wc);
                    ea0 = fma2(wc2, bp0[e], ea0);
                    ea1 = fma2(wc2, bp1[e], ea1);
                }
            }
            __syncthreads();   // BAR3: scaleP/wP visible

            // ---- accumulators (registers only) ----
            {
#pragma unroll
                for (int c = 0; c < 4; ++c) {
                    int rp = 4 * gru + c;
                    ull prod = mul2(mul2(sh_wP[rp], bt[c]), ebr[c]);
                    cacc[c] = fma2(sh_scaleP[rp], cacc[c], prod);
                }
                gacc[0] = fma2(sh_scaleP[q], gacc[0], mul2(mul2(sh_wP[q], ea0), xr0));
                gacc[1] = fma2(sh_scaleP[q + 4], gacc[1],
                               mul2(mul2(sh_wP[q + 4], ea1), xr1));
            }
        } // steps

        // ---- finalize ----
        __syncthreads();
        if (p >= base) {
            const int qi = p - base;
#pragma unroll
            for (int c = 0; c < 4; ++c) sh_betaP[4 * gru + c][k] = cacc[c];
            __syncthreads();

            if (t < 16) {
                float sum = 0.f;
                const ull* Crow = sh_betaP[t >> 1];
                const bool hi = (t & 1);
#pragma unroll 8
                for (int e = 0; e < 128; ++e) {
                    float2 v = unpack2(Crow[e]);
                    sum = fmaf(Wo[e], hi ? v.y : v.x, sum);
                }
                out[(size_t)(b0 + t) * nq + qi] = __fdividef(sum, sh_l[t]) + bo[0];
            }
            {
                float inv = __fdividef(1.f, (float)(p + 1));
                size_t wbase = (size_t)64 * nq;
#pragma unroll
                for (int cc = 0; cc < 2; ++cc) {
                    int rp = q + 4 * cc;
                    float2 gv = unpack2(gacc[cc]);
                    out[wbase + ((size_t)(b0 + 2 * rp) * nq + qi) * 64 + (t & 63)] =
                        __fdividef(gv.x, sh_l[2 * rp]) * inv;
                    out[wbase + ((size_t)(b0 + 2 * rp + 1) * nq + qi) * 64 + (t & 63)] =
                        __fdividef(gv.y, sh_l[2 * rp + 1]) * inv;
                }
            }
        }
        __syncthreads();
    } // segments
#undef WAITC
#undef ISSUE_ONE
}

// ---------------- launch ----------------
extern "C" void kernel_launch(void* const* d_in, const int* in_sizes, int n_in,
                              void* d_out, int out_size) {
    const float* x     = (const float*)d_in[0];
    const float* W_emb = (const float*)d_in[1];
    const float* b_emb = (const float*)d_in[2];
    const float* Wi_a  = (const float*)d_in[3];
    const float* Wh_a  = (const float*)d_in[4];
    const float* bi_a  = (const float*)d_in[5];
    const float* bh_a  = (const float*)d_in[6];
    const float* Wi_b  = (const float*)d_in[7];
    const float* Wh_b  = (const float*)d_in[8];
    const float* bi_b  = (const float*)d_in[9];
    const float* bh_b  = (const float*)d_in[10];
    const float* Wa    = (const float*)d_in[11];
    const float* ba    = (const float*)d_in[12];
    const float* Wb    = (const float*)d_in[13];
    const float* bb    = (const float*)d_in[14];
    const float* Wo    = (const float*)d_in[15];
    const float* bo    = (const float*)d_in[16];
    float* out = (float*)d_out;

    int nq = out_size / (64 * 65);

    static int smem_set = 0;
    if (!smem_set) {
        cudaFuncSetAttribute(retain_main,
                             cudaFuncAttributeMaxDynamicSharedMemorySize, SMEM_TOTAL);
        smem_set = 1;
    }

    prep_transpose<<<256, 256>>>(x, Wh_a, Wh_b, Wi_a, Wi_b, Wb, W_emb, Wo);
    emb_kernel<<<Tn * Bn, 128>>>(x, b_emb);
    gi_kernel<<<Tn * Bn, 256>>>(bi_a, bi_b);
    retain_main<<<128, 256, SMEM_TOTAL>>>(bh_a, bh_b, Wa, ba, bb, Wo, bo, nq, out);
}